// round 9
// baseline (speedup 1.0000x reference)
#include <cuda_runtime.h>
#include <stdint.h>

#define NTHREADS 1024               // K2 block
#define NWARPS (NTHREADS / 32)
#define NT1 512                     // K1 block
#define NW1 (NT1 / 32)
#define HBITS 13
#define NBINS (1 << HBITS)
#define CAP 2048                    // per-row candidate capacity (K2)
#define HALF_CAP 1024               // per-half candidate capacity (K1)
#define SAMP 16384                  // per-half sample size
#define TARGET_HALF 750             // desired E[count] per half
#define SAMPLING_EPS 1e-5f
#define MAXB 256

// ---------------- global scratch (plain stores; no init needed) -----------
__device__ unsigned long long g_cand[MAXB][2][HALF_CAP];   // 4 MB
__device__ int    g_cnt [MAXB][2];
__device__ float  g_sums[MAXB][2];
__device__ float  g_thrf[MAXB][2];

// order-preserving float -> uint32 map (and inverse)
__device__ __forceinline__ unsigned mono(float f) {
    unsigned u = __float_as_uint(f);
    return u ^ ((unsigned)(((int)u) >> 31) | 0x80000000u);
}
__device__ __forceinline__ float inv_mono(unsigned m) {
    unsigned u = (m & 0x80000000u) ? (m ^ 0x80000000u) : ~m;
    return __uint_as_float(u);
}

// one bitonic round's register-resident phases (j = jstart..1, jstart<=32).
__device__ __forceinline__ void reg_round(unsigned long long& a, unsigned long long& b,
                                          int i0, int i1, int lane, int kk, int jstart) {
    const bool upa = ((i0 & kk) == 0);
    const bool upb = ((i1 & kk) == 0);
#pragma unroll
    for (int j = 32; j >= 1; j >>= 1) {
        if (j > jstart) continue;
        if (j == 32) {
            unsigned long long lo = a < b ? a : b;
            unsigned long long hi = a < b ? b : a;
            a = upa ? lo : hi;
            b = upa ? hi : lo;
        } else {
            const bool lower = ((lane & j) == 0);
            unsigned long long pa = __shfl_xor_sync(0xFFFFFFFFu, a, j);
            unsigned long long pb = __shfl_xor_sync(0xFFFFFFFFu, b, j);
            bool keepMinA = (lower == upa);
            bool keepMinB = (lower == upb);
            a = keepMinA ? (a < pa ? a : pa) : (a > pa ? a : pa);
            b = keepMinB ? (b < pb ? b : pb) : (b > pb ? b : pb);
        }
    }
}

// block-wide suffix-scan of 13-bit histogram; largest bin with suffix >= need.
// Returns bin; *s_above = suffix strictly above it. Template on block size.
template <int NT>
__device__ int find_bin(unsigned* hist, unsigned need, unsigned* wu,
                        unsigned* s_bin, unsigned* s_above) {
    const int t = threadIdx.x, lane = t & 31, warp = t >> 5;
    constexpr int NW = NT / 32, BPTc = NBINS / NT;
    if (t == 0) { *s_bin = 0u; *s_above = 0u; }
    __syncthreads();                 // hist atomics complete + init
    unsigned cnt[BPTc];
    unsigned csum = 0;
#pragma unroll
    for (int b = 0; b < BPTc; b++) { cnt[b] = hist[t * BPTc + b]; csum += cnt[b]; }
    unsigned iv = csum;
#pragma unroll
    for (int off = 1; off < 32; off <<= 1) {
        unsigned nb = __shfl_up_sync(0xFFFFFFFFu, iv, off);
        if (lane >= off) iv += nb;
    }
    if (lane == 31) wu[warp] = iv;
    __syncthreads();
    if (warp == 0) {
        unsigned wv = (lane < NW) ? wu[lane] : 0u;
#pragma unroll
        for (int off = 1; off < 32; off <<= 1) {
            unsigned nb = __shfl_up_sync(0xFFFFFFFFu, wv, off);
            if (lane >= off) wv += nb;
        }
        if (lane < NW) wu[lane] = wv;
    }
    __syncthreads();
    unsigned incl = iv + (warp ? wu[warp - 1] : 0u);
    unsigned Total = wu[NW - 1];
    unsigned above = Total - incl;
    unsigned acc = above, prev = above;
#pragma unroll
    for (int b = BPTc - 1; b >= 0; b--) {
        acc += cnt[b];
        if (acc >= need && prev < need) { *s_bin = (unsigned)(t * BPTc + b); *s_above = prev; }
        prev = acc;
    }
    __syncthreads();
    return (int)*s_bin;
}

// ======================================================================
// K1: grid = B*2, 512 thr, occ 2 — one wave over all SMs.
// Per CTA (row, half): two-level sampled threshold on own half,
// one streaming pass: sum-exp + candidate collect -> global scratch.
// ======================================================================
__global__ __launch_bounds__(NT1, 2) void k1_stream(const float* __restrict__ logits, int V) {
    const int bid = blockIdx.x;
    const int row = bid >> 1, half = bid & 1;
    const int t = threadIdx.x;
    const int lane = t & 31, warp = t >> 5;

    __shared__ unsigned hist[NBINS];                 // 32 KB
    __shared__ __align__(16) unsigned long long skey[HALF_CAP];  // 8 KB
    __shared__ unsigned wu[NW1];
    __shared__ float wf[NW1];
    __shared__ unsigned s_bin, s_above;
    __shared__ int s_cnt;

    const int chunk = (V >> 1) & ~3;                 // keep float4 alignment
    const int start = half ? chunk : 0;
    const int len   = half ? (V - chunk) : chunk;
    const float* __restrict__ x = logits + (size_t)row * V + start;
    const int len4 = len >> 2;
    const float4* __restrict__ x4 = (const float4*)x;

    for (int z = t; z < NBINS; z += NT1) hist[z] = 0u;
    if (t == 0) s_cnt = 0;
    __syncthreads();

    // ---- level 1: coarse 13-bit histogram of sample ----
    const int SQ = min(SAMP, len & ~3) >> 2;
    for (int i = t; i < SQ; i += NT1) {
        float4 v = x4[i];
        atomicAdd(&hist[mono(v.x) >> (32 - HBITS)], 1u);
        atomicAdd(&hist[mono(v.y) >> (32 - HBITS)], 1u);
        atomicAdd(&hist[mono(v.z) >> (32 - HBITS)], 1u);
        atomicAdd(&hist[mono(v.w) >> (32 - HBITS)], 1u);
    }
    const unsigned need_samp = (unsigned)max(1ll,
        ((long long)TARGET_HALF * (long long)(SQ * 4)) / (long long)len);
    const int b1 = find_bin<NT1>(hist, need_samp, wu, &s_bin, &s_above);
    const unsigned need2 = need_samp - s_above;

    // ---- level 2: fine histogram within coarse bin (L1-hot re-read) ----
    for (int z = t; z < NBINS; z += NT1) hist[z] = 0u;
    __syncthreads();
    for (int i = t; i < SQ; i += NT1) {
        float4 v = x4[i];
        unsigned u;
        u = mono(v.x); if ((int)(u >> 19) == b1) atomicAdd(&hist[(u >> 6) & 0x1FFFu], 1u);
        u = mono(v.y); if ((int)(u >> 19) == b1) atomicAdd(&hist[(u >> 6) & 0x1FFFu], 1u);
        u = mono(v.z); if ((int)(u >> 19) == b1) atomicAdd(&hist[(u >> 6) & 0x1FFFu], 1u);
        u = mono(v.w); if ((int)(u >> 19) == b1) atomicAdd(&hist[(u >> 6) & 0x1FFFu], 1u);
    }
    const int fb = find_bin<NT1>(hist, need2, wu, &s_bin, &s_above);
    const unsigned thr = ((unsigned)b1 << 19) | ((unsigned)fb << 6);
    const float thr_f = inv_mono(thr);

    // ---- single streaming pass: sum-exp + collect (one branch per float4) ----
    float s0 = 0.f, s1 = 0.f, s2 = 0.f, s3 = 0.f;
    auto procF = [&](float4 v, int gbase) {
        s0 += __expf(v.x); s1 += __expf(v.y);
        s2 += __expf(v.z); s3 += __expf(v.w);
        bool p0 = v.x >= thr_f, p1 = v.y >= thr_f, p2 = v.z >= thr_f, p3 = v.w >= thr_f;
        if (p0 | p1 | p2 | p3) {
            if (p0) { int p = atomicAdd(&s_cnt, 1); if (p < HALF_CAP) skey[p] = ((unsigned long long)mono(v.x) << 32) | (unsigned)~(unsigned)(gbase + 0); }
            if (p1) { int p = atomicAdd(&s_cnt, 1); if (p < HALF_CAP) skey[p] = ((unsigned long long)mono(v.y) << 32) | (unsigned)~(unsigned)(gbase + 1); }
            if (p2) { int p = atomicAdd(&s_cnt, 1); if (p < HALF_CAP) skey[p] = ((unsigned long long)mono(v.z) << 32) | (unsigned)~(unsigned)(gbase + 2); }
            if (p3) { int p = atomicAdd(&s_cnt, 1); if (p < HALF_CAP) skey[p] = ((unsigned long long)mono(v.w) << 32) | (unsigned)~(unsigned)(gbase + 3); }
        }
    };
    int i = t;
    for (; i + 3 * NT1 < len4; i += 4 * NT1) {
        float4 a = x4[i];
        float4 b = x4[i + NT1];
        float4 c = x4[i + 2 * NT1];
        float4 d = x4[i + 3 * NT1];
        procF(a, start + 4 * i);
        procF(b, start + 4 * (i + NT1));
        procF(c, start + 4 * (i + 2 * NT1));
        procF(d, start + 4 * (i + 3 * NT1));
    }
    for (; i < len4; i += NT1) procF(x4[i], start + 4 * i);
    for (int j = (len4 << 2) + t; j < len; j += NT1) {
        float v = x[j];
        s0 += __expf(v);
        if (v >= thr_f) { int p = atomicAdd(&s_cnt, 1); if (p < HALF_CAP) skey[p] = ((unsigned long long)mono(v) << 32) | (unsigned)~(unsigned)(start + j); }
    }
    float s = (s0 + s1) + (s2 + s3);
#pragma unroll
    for (int off = 16; off; off >>= 1)
        s += __shfl_xor_sync(0xFFFFFFFFu, s, off);
    if (lane == 0) wf[warp] = s;
    __syncthreads();                 // skey writes + s_cnt final + wf visible

    // ---- publish to global scratch ----
    const int m = min(s_cnt, HALF_CAP);
    for (int z = t; z < m; z += NT1) g_cand[row][half][z] = skey[z];
    if (t == 0) {
        float stot = 0.f;
#pragma unroll
        for (int w2 = 0; w2 < NW1; w2++) stot += wf[w2];
        g_sums[row][half] = stot;
        g_cnt[row][half]  = s_cnt;   // unclamped: K2 detects overflow
        g_thrf[row][half] = thr_f;
    }
}

// ======================================================================
// K2: grid = B. Load candidates (L2-hot), verify, (rare exact fallback),
// hybrid bitonic sort, min-p/top-k/top-p, race sampling, top-20, rank.
// ======================================================================
__global__ __launch_bounds__(NTHREADS, 1) void k2_finish(
    const float* __restrict__ logits,
    const float* __restrict__ temperature,
    const float* __restrict__ min_p,
    const int*   __restrict__ top_k,
    const float* __restrict__ top_p,
    const float* __restrict__ q,
    float* __restrict__ out,
    int B, int V, int C)
{
    const int row = blockIdx.x;
    const int t = threadIdx.x;
    const int lane = t & 31, warp = t >> 5;

    // 32KB union: hist[8192 u32] OR key[2048 u64] | e[2048 f32] | hd[2048 f32]
    __shared__ __align__(16) unsigned char sbuf[NBINS * 4];
    __shared__ float wf[NWARPS];
    __shared__ unsigned wu[NWARPS];
    __shared__ int wi[NWARPS], wr[NWARPS];
    __shared__ unsigned s_bin, s_above;
    __shared__ int s_cnt, s_m, s_S, s_rank, s_sampled, s_rstar, s_chk;

    unsigned* hist = (unsigned*)sbuf;
    unsigned long long* key = (unsigned long long*)sbuf;
    float* e  = (float*)(sbuf + CAP * 8);
    float* hd = (float*)(sbuf + CAP * 8 + CAP * 4);

    if (t == 0) { s_m = 0; s_S = 0; s_rank = 0; s_chk = 0; }
    __syncthreads();

    const int c0 = g_cnt[row][0], c1 = g_cnt[row][1];
    const float thrmax = fmaxf(g_thrf[row][0], g_thrf[row][1]);
    const float lZ = logf(g_sums[row][0] + g_sums[row][1]);
    const int n0 = min(c0, HALF_CAP), n1 = min(c1, HALF_CAP);
    int n = n0 + n1;

    for (int z = t; z < n0; z += NTHREADS) key[z] = g_cand[row][0][z];
    for (int z = t; z < n1; z += NTHREADS) key[n0 + z] = g_cand[row][1][z];
    __syncthreads();

    // verification: all elements >= thrmax are present; need top-`needed` covered
    int kclip = top_k[row];
    kclip = max(1, min(kclip, V));
    const int needed = min(max(kclip, C), CAP);
    for (int z = t; z < n; z += NTHREADS)
        if (inv_mono((unsigned)(key[z] >> 32)) >= thrmax) atomicAdd(&s_chk, 1);
    __syncthreads();

    if (c0 > HALF_CAP || c1 > HALF_CAP || s_chk < needed) {
        // ---- exact fallback: full-row coarse histogram + recollect (rare) ----
        const float* __restrict__ x = logits + (size_t)row * V;
        const int V4 = V >> 2;
        const float4* __restrict__ x4 = (const float4*)x;
        for (int z = t; z < NBINS; z += NTHREADS) hist[z] = 0u;   // clobbers key
        __syncthreads();
        for (int ii = t; ii < V4; ii += NTHREADS) {
            float4 v = x4[ii];
            atomicAdd(&hist[mono(v.x) >> (32 - HBITS)], 1u);
            atomicAdd(&hist[mono(v.y) >> (32 - HBITS)], 1u);
            atomicAdd(&hist[mono(v.z) >> (32 - HBITS)], 1u);
            atomicAdd(&hist[mono(v.w) >> (32 - HBITS)], 1u);
        }
        for (int j = (V4 << 2) + t; j < V; j += NTHREADS)
            atomicAdd(&hist[mono(x[j]) >> (32 - HBITS)], 1u);
        int b2 = find_bin<NTHREADS>(hist, (unsigned)needed, wu, &s_bin, &s_above);
        unsigned thr2 = (unsigned)b2 << 19;
        if (t == 0) s_cnt = 0;
        __syncthreads();
        for (int ii = t; ii < V4; ii += NTHREADS) {
            float4 v = x4[ii];
            unsigned u;
            u = mono(v.x); if (u >= thr2) { int p = atomicAdd(&s_cnt, 1); if (p < CAP) key[p] = ((unsigned long long)u << 32) | (unsigned)~(unsigned)(4 * ii + 0); }
            u = mono(v.y); if (u >= thr2) { int p = atomicAdd(&s_cnt, 1); if (p < CAP) key[p] = ((unsigned long long)u << 32) | (unsigned)~(unsigned)(4 * ii + 1); }
            u = mono(v.z); if (u >= thr2) { int p = atomicAdd(&s_cnt, 1); if (p < CAP) key[p] = ((unsigned long long)u << 32) | (unsigned)~(unsigned)(4 * ii + 2); }
            u = mono(v.w); if (u >= thr2) { int p = atomicAdd(&s_cnt, 1); if (p < CAP) key[p] = ((unsigned long long)u << 32) | (unsigned)~(unsigned)(4 * ii + 3); }
        }
        for (int j = (V4 << 2) + t; j < V; j += NTHREADS) {
            unsigned u = mono(x[j]);
            if (u >= thr2) { int p = atomicAdd(&s_cnt, 1); if (p < CAP) key[p] = ((unsigned long long)u << 32) | (unsigned)~(unsigned)j; }
        }
        __syncthreads();
        n = min(s_cnt, CAP);
    }
    for (int z = n + t; z < CAP; z += NTHREADS) key[z] = 0ULL;  // sentinel
    __syncthreads();

    // ---------------- hybrid bitonic sort (ascending) -------------------------
    const int i0 = 64 * warp + lane;
    const int i1 = i0 + 32;
    {
        unsigned long long a = key[i0], b = key[i1];
#pragma unroll
        for (int kk = 2; kk <= 64; kk <<= 1)
            reg_round(a, b, i0, i1, lane, kk, (kk >> 1) > 32 ? 32 : (kk >> 1));
        key[i0] = a; key[i1] = b;
        __syncthreads();
        for (int kk = 128; kk <= CAP; kk <<= 1) {
            for (int j = kk >> 1; j >= 64; j >>= 1) {
#pragma unroll
                for (int w2 = 0; w2 < CAP / NTHREADS; w2++) {
                    int idx = t + w2 * NTHREADS;
                    int l2 = idx ^ j;
                    if (l2 > idx) {
                        unsigned long long av = key[idx], bv = key[l2];
                        bool sw = ((idx & kk) == 0) ? (av > bv) : (av < bv);
                        if (sw) { key[idx] = bv; key[l2] = av; }
                    }
                }
                __syncthreads();
            }
            a = key[i0]; b = key[i1];
            reg_round(a, b, i0, i1, lane, kk, 32);
            key[i0] = a; key[i1] = b;
            __syncthreads();
        }
    }

#define DKEY(r) (key[CAP - 1 - (r)])
#define DVAL(r) inv_mono((unsigned)(DKEY(r) >> 32))
#define DIDX(r) ((int)(~(unsigned)DKEY(r)))

    // ---------------- per-row scalars (rmax = top candidate) ------------------
    const float rmax = DVAL(0);
    const float temp = temperature[row];
    const float mp   = min_p[row];
    const float tp   = top_p[row];
    const int kk_ = kclip;
    const float t_mp = rmax + temp * logf(mp);

    for (int r = t; r < n; r += NTHREADS)
        if (DVAL(r) >= t_mp) atomicAdd(&s_m, 1);
    __syncthreads();
    const int mcnt = s_m;

    if (mcnt >= kk_) {
        float kth = DVAL(kk_ - 1);
        for (int r = t; r < n; r += NTHREADS)
            if (DVAL(r) >= kth) atomicAdd(&s_S, 1);
    }
    __syncthreads();
    const int S = (mcnt >= kk_) ? min(s_S, CAP) : mcnt;

    const bool greedy = (temp < SAMPLING_EPS);
    int sampled, rstar;

    if (!greedy) {
        const float lt0 = DVAL(0) / temp;
        for (int r = t; r < CAP; r += NTHREADS) {
            float ev = 0.f;
            if (r < S) ev = expf(DVAL(r) / temp - lt0);
            e[r] = ev;
        }
        __syncthreads();

        float a0 = e[2 * t], a1 = e[2 * t + 1];
        float tsum = a0 + a1;
        float sv = tsum;
#pragma unroll
        for (int off = 1; off < 32; off <<= 1) {
            float nb = __shfl_up_sync(0xFFFFFFFFu, sv, off);
            if (lane >= off) sv += nb;
        }
        if (lane == 31) wf[warp] = sv;
        __syncthreads();
        if (warp == 0) {
            float wv = wf[lane];
#pragma unroll
            for (int off = 1; off < 32; off <<= 1) {
                float nb = __shfl_up_sync(0xFFFFFFFFu, wv, off);
                if (lane >= off) wv += nb;
            }
            wf[lane] = wv;
        }
        __syncthreads();
        float inclf = sv + (warp ? wf[warp - 1] : 0.f);
        const float Z = wf[NWARPS - 1];
        float excl = inclf - tsum;
        hd[2 * t]     = excl;
        hd[2 * t + 1] = excl + a0;
        __syncthreads();

        const float c1f = (1.f - tp) * Z;
        const float* __restrict__ qrow = q + (size_t)row * V;
        float best = -1.f;
        int bidx = 0x7FFFFFFF, brr = 0;
        for (int r = t; r < S; r += NTHREADS) {
            if (r == 0 || (Z - hd[r]) > c1f) {
                int id = DIDX(r);
                float qv = qrow[id];
                float ex = -logf(fmaxf(qv, 1e-10f));
                float sc = e[r] / ex;
                if (sc > best || (sc == best && id < bidx)) { best = sc; bidx = id; brr = r; }
            }
        }
#pragma unroll
        for (int off = 16; off; off >>= 1) {
            float ob = __shfl_down_sync(0xFFFFFFFFu, best, off);
            int   oi = __shfl_down_sync(0xFFFFFFFFu, bidx, off);
            int   orr = __shfl_down_sync(0xFFFFFFFFu, brr, off);
            if (ob > best || (ob == best && oi < bidx)) { best = ob; bidx = oi; brr = orr; }
        }
        if (lane == 0) { wf[warp] = best; wi[warp] = bidx; wr[warp] = brr; }
        __syncthreads();
        if (warp == 0) {
            best = wf[lane]; bidx = wi[lane]; brr = wr[lane];
#pragma unroll
            for (int off = 16; off; off >>= 1) {
                float ob = __shfl_down_sync(0xFFFFFFFFu, best, off);
                int   oi = __shfl_down_sync(0xFFFFFFFFu, bidx, off);
                int   orr = __shfl_down_sync(0xFFFFFFFFu, brr, off);
                if (ob > best || (ob == best && oi < bidx)) { best = ob; bidx = oi; brr = orr; }
            }
            if (lane == 0) { s_sampled = bidx; s_rstar = brr; }
        }
        __syncthreads();
        sampled = s_sampled;
        rstar = s_rstar;
    } else {
        sampled = DIDX(0);
        rstar = 0;
    }

    const float vstar = DVAL(rstar);
    const float tlp = vstar - lZ;
    for (int r = t; r < n; r += NTHREADS) {
        if ((DVAL(r) - lZ) >= tlp) atomicAdd(&s_rank, 1);
    }
    __syncthreads();

    if (t == 0) {
        out[row] = (float)sampled;
        out[(size_t)B + (size_t)row * C] = (float)sampled;
        out[(size_t)B + (size_t)B * C + (size_t)row * C] = tlp;
        out[(size_t)B + 2 * (size_t)B * C + row] = (float)s_rank;
    }
    if (t >= 1 && t < C) {
        int r = t - 1;
        unsigned long long kv = DKEY(r);
        out[(size_t)B + (size_t)row * C + t] = (float)(~(unsigned)kv);
        out[(size_t)B + (size_t)B * C + (size_t)row * C + t] = inv_mono((unsigned)(kv >> 32)) - lZ;
    }
#undef DKEY
#undef DVAL
#undef DIDX
}

// ======================================================================
extern "C" void kernel_launch(void* const* d_in, const int* in_sizes, int n_in,
                              void* d_out, int out_size) {
    const float* logits      = (const float*)d_in[0];
    const float* temperature = (const float*)d_in[1];
    const float* min_p       = (const float*)d_in[2];
    const int*   top_k       = (const int*)d_in[3];
    const float* top_p       = (const float*)d_in[4];
    const float* q           = (const float*)d_in[5];

    int B = in_sizes[1];
    int V = in_sizes[0] / B;
    int C = (out_size / B - 2) / 2;   // num_logprobs + 1

    k1_stream<<<B * 2, NT1>>>(logits, V);
    k2_finish<<<B, NTHREADS>>>(logits, temperature, min_p, top_k, top_p, q,
                               (float*)d_out, B, V, C);
}

// round 10
// speedup vs baseline: 2.1154x; 2.1154x over previous
#include <cuda_runtime.h>
#include <stdint.h>

#define NTHREADS 1024
#define NWARPS (NTHREADS / 32)
#define HBITS 13
#define NBINS (1 << HBITS)          // 8192
#define BPT (NBINS / NTHREADS)      // 8
#define CAP 2048
#define SAMP 16384
#define TARGET 1500
#define SAMPLING_EPS 1e-5f
#define SMEMSZ (64 * 1024)

// order-preserving float -> uint32 map (and inverse)
__device__ __forceinline__ unsigned mono(float f) {
    unsigned u = __float_as_uint(f);
    return u ^ ((unsigned)(((int)u) >> 31) | 0x80000000u);
}
__device__ __forceinline__ float inv_mono(unsigned m) {
    unsigned u = (m & 0x80000000u) ? (m ^ 0x80000000u) : ~m;
    return __uint_as_float(u);
}

// block-wide suffix-scan of 13-bit histogram; largest bin with suffix >= need.
__device__ int find_bin(unsigned* hist, unsigned need, unsigned* wu,
                        unsigned* s_bin, unsigned* s_above) {
    const int t = threadIdx.x, lane = t & 31, warp = t >> 5;
    if (t == 0) { *s_bin = 0u; *s_above = 0u; }
    __syncthreads();
    unsigned cnt[BPT];
    unsigned csum = 0;
#pragma unroll
    for (int b = 0; b < BPT; b++) { cnt[b] = hist[t * BPT + b]; csum += cnt[b]; }
    unsigned iv = csum;
#pragma unroll
    for (int off = 1; off < 32; off <<= 1) {
        unsigned nb = __shfl_up_sync(0xFFFFFFFFu, iv, off);
        if (lane >= off) iv += nb;
    }
    if (lane == 31) wu[warp] = iv;
    __syncthreads();
    if (warp == 0) {
        unsigned wv = wu[lane];
#pragma unroll
        for (int off = 1; off < 32; off <<= 1) {
            unsigned nb = __shfl_up_sync(0xFFFFFFFFu, wv, off);
            if (lane >= off) wv += nb;
        }
        wu[lane] = wv;
    }
    __syncthreads();
    unsigned incl = iv + (warp ? wu[warp - 1] : 0u);
    unsigned Total = wu[NWARPS - 1];
    unsigned above = Total - incl;
    unsigned acc = above, prev = above;
#pragma unroll
    for (int b = BPT - 1; b >= 0; b--) {
        acc += cnt[b];
        if (acc >= need && prev < need) { *s_bin = (unsigned)(t * BPT + b); *s_above = prev; }
        prev = acc;
    }
    __syncthreads();
    return (int)*s_bin;
}

// in-place exclusive scan of cnt[8192]
__device__ void excl_scan(unsigned* cnt, unsigned* wu) {
    const int t = threadIdx.x, lane = t & 31, warp = t >> 5;
    unsigned c[BPT], inc[BPT];
    unsigned run = 0;
#pragma unroll
    for (int b = 0; b < BPT; b++) { c[b] = cnt[t * BPT + b]; run += c[b]; inc[b] = run; }
    unsigned iv = run;
#pragma unroll
    for (int off = 1; off < 32; off <<= 1) {
        unsigned nb = __shfl_up_sync(0xFFFFFFFFu, iv, off);
        if (lane >= off) iv += nb;
    }
    if (lane == 31) wu[warp] = iv;
    __syncthreads();
    if (warp == 0) {
        unsigned wv = wu[lane];
#pragma unroll
        for (int off = 1; off < 32; off <<= 1) {
            unsigned nb = __shfl_up_sync(0xFFFFFFFFu, wv, off);
            if (lane >= off) wv += nb;
        }
        wu[lane] = wv;
    }
    __syncthreads();
    unsigned base = (iv - run) + (warp ? wu[warp - 1] : 0u);
#pragma unroll
    for (int b = 0; b < BPT; b++) cnt[t * BPT + b] = base + inc[b] - c[b];
    __syncthreads();
}

// ======================================================================
// Fused sampler (R8 structure):
//   two-level sampled threshold -> thr (26-bit)
//   ONE full pass: sum-exp + candidate collect (+ exact fallback, ~never)
//   COUNTING sort (bin+scan+scatter+tiny insertion) instead of bitonic
//   min-p/top-k/top-p, race sampling, top-20 logprobs, rank
// Dynamic smem (64KB): key[2048]u64 | cnt[8192]u32 (later e/hd) | keyB[2048]u64
// ======================================================================
__global__ __launch_bounds__(NTHREADS, 1) void sampler_fused(
    const float* __restrict__ logits,
    const float* __restrict__ temperature,
    const float* __restrict__ min_p,
    const int*   __restrict__ top_k,
    const float* __restrict__ top_p,
    const float* __restrict__ q,
    float* __restrict__ out,
    int B, int V, int C)
{
    extern __shared__ __align__(16) unsigned char dynbuf[];
    unsigned long long* key  = (unsigned long long*)dynbuf;            // 16KB
    unsigned*           cnt  = (unsigned*)(dynbuf + 16384);            // 32KB (hist/counters)
    unsigned long long* keyB = (unsigned long long*)(dynbuf + 49152);  // 16KB
    float* e  = (float*)(dynbuf + 16384);          // overlays cnt after sort
    float* hd = (float*)(dynbuf + 16384 + 8192);

    const int row = blockIdx.x;
    const int t = threadIdx.x;
    const int lane = t & 31, warp = t >> 5;

    __shared__ float wf[NWARPS];
    __shared__ unsigned wu[NWARPS];
    __shared__ int wi[NWARPS], wr[NWARPS];
    __shared__ unsigned s_bin, s_above, s_kmax;
    __shared__ int s_cnt, s_m, s_S, s_rank, s_sampled, s_rstar;
    __shared__ float s_lz;

    if (t == 0) { s_cnt = 0; s_m = 0; s_S = 0; s_rank = 0; s_kmax = 0u; }
    for (int z = t; z < NBINS; z += NTHREADS) cnt[z] = 0u;
    __syncthreads();

    const float* __restrict__ x = logits + (size_t)row * V;
    const int V4 = V >> 2;
    const float4* __restrict__ x4 = (const float4*)x;

    // ------------- level 1: coarse 13-bit histogram of 16K sample -------------
    const int SQ = min(SAMP, V & ~3) >> 2;
    for (int i = t; i < SQ; i += NTHREADS) {
        float4 v = x4[i];
        atomicAdd(&cnt[mono(v.x) >> (32 - HBITS)], 1u);
        atomicAdd(&cnt[mono(v.y) >> (32 - HBITS)], 1u);
        atomicAdd(&cnt[mono(v.z) >> (32 - HBITS)], 1u);
        atomicAdd(&cnt[mono(v.w) >> (32 - HBITS)], 1u);
    }
    const unsigned need_samp = (unsigned)max(1ll,
        ((long long)TARGET * (long long)(SQ * 4)) / (long long)V);
    const int b1 = find_bin(cnt, need_samp, wu, &s_bin, &s_above);
    const unsigned need2 = need_samp - s_above;

    // ------------- level 2: fine histogram within coarse bin -------------
    for (int z = t; z < NBINS; z += NTHREADS) cnt[z] = 0u;
    __syncthreads();
    for (int i = t; i < SQ; i += NTHREADS) {
        float4 v = x4[i];
        unsigned u;
        u = mono(v.x); if ((int)(u >> 19) == b1) atomicAdd(&cnt[(u >> 6) & 0x1FFFu], 1u);
        u = mono(v.y); if ((int)(u >> 19) == b1) atomicAdd(&cnt[(u >> 6) & 0x1FFFu], 1u);
        u = mono(v.z); if ((int)(u >> 19) == b1) atomicAdd(&cnt[(u >> 6) & 0x1FFFu], 1u);
        u = mono(v.w); if ((int)(u >> 19) == b1) atomicAdd(&cnt[(u >> 6) & 0x1FFFu], 1u);
    }
    const int fb = find_bin(cnt, need2, wu, &s_bin, &s_above);
    unsigned thrkey = ((unsigned)b1 << 19) | ((unsigned)fb << 6);
    const float thr_f = inv_mono(thrkey);

    // ------------- single full pass: sum-exp + collect -------------
    float sx0 = 0.f, sx1 = 0.f, sx2 = 0.f, sx3 = 0.f;
    auto procF = [&](float4 v, int base) {
        sx0 += __expf(v.x); sx1 += __expf(v.y);
        sx2 += __expf(v.z); sx3 += __expf(v.w);
        bool p0 = v.x >= thr_f, p1 = v.y >= thr_f, p2 = v.z >= thr_f, p3 = v.w >= thr_f;
        if (p0 | p1 | p2 | p3) {
            if (p0) { unsigned u = mono(v.x); atomicMax(&s_kmax, u); int p = atomicAdd(&s_cnt, 1); if (p < CAP) key[p] = ((unsigned long long)u << 32) | (unsigned)~(unsigned)(base + 0); }
            if (p1) { unsigned u = mono(v.y); atomicMax(&s_kmax, u); int p = atomicAdd(&s_cnt, 1); if (p < CAP) key[p] = ((unsigned long long)u << 32) | (unsigned)~(unsigned)(base + 1); }
            if (p2) { unsigned u = mono(v.z); atomicMax(&s_kmax, u); int p = atomicAdd(&s_cnt, 1); if (p < CAP) key[p] = ((unsigned long long)u << 32) | (unsigned)~(unsigned)(base + 2); }
            if (p3) { unsigned u = mono(v.w); atomicMax(&s_kmax, u); int p = atomicAdd(&s_cnt, 1); if (p < CAP) key[p] = ((unsigned long long)u << 32) | (unsigned)~(unsigned)(base + 3); }
        }
    };
    int i = t;
    for (; i + 3 * NTHREADS < V4; i += 4 * NTHREADS) {
        float4 a = x4[i];
        float4 b = x4[i + NTHREADS];
        float4 c = x4[i + 2 * NTHREADS];
        float4 d = x4[i + 3 * NTHREADS];
        procF(a, 4 * i);
        procF(b, 4 * (i + NTHREADS));
        procF(c, 4 * (i + 2 * NTHREADS));
        procF(d, 4 * (i + 3 * NTHREADS));
    }
    for (; i < V4; i += NTHREADS) procF(x4[i], 4 * i);
    for (int j = (V4 << 2) + t; j < V; j += NTHREADS) {
        float v = x[j];
        sx0 += __expf(v);
        if (v >= thr_f) { unsigned u = mono(v); atomicMax(&s_kmax, u); int p = atomicAdd(&s_cnt, 1); if (p < CAP) key[p] = ((unsigned long long)u << 32) | (unsigned)~(unsigned)j; }
    }
    float s = (sx0 + sx1) + (sx2 + sx3);
#pragma unroll
    for (int off = 16; off; off >>= 1)
        s += __shfl_xor_sync(0xFFFFFFFFu, s, off);
    if (lane == 0) wf[warp] = s;
    __syncthreads();                 // key + s_cnt + s_kmax final
    if (t == 0) {
        float stot = 0.f;
#pragma unroll
        for (int w2 = 0; w2 < NWARPS; w2++) stot += wf[w2];
        s_lz = logf(stot);
    }
    __syncthreads();

    // ------------- check + exact fallback (statistically never) -------------
    int kclip = top_k[row];
    kclip = max(1, min(kclip, V));
    const int needed = min(max(kclip, C), CAP);
    if (s_cnt < needed || s_cnt > CAP) {
        for (int z = t; z < NBINS; z += NTHREADS) cnt[z] = 0u;
        __syncthreads();
        for (int ii = t; ii < V4; ii += NTHREADS) {
            float4 v = x4[ii];
            atomicAdd(&cnt[mono(v.x) >> (32 - HBITS)], 1u);
            atomicAdd(&cnt[mono(v.y) >> (32 - HBITS)], 1u);
            atomicAdd(&cnt[mono(v.z) >> (32 - HBITS)], 1u);
            atomicAdd(&cnt[mono(v.w) >> (32 - HBITS)], 1u);
        }
        for (int j = (V4 << 2) + t; j < V; j += NTHREADS)
            atomicAdd(&cnt[mono(x[j]) >> (32 - HBITS)], 1u);
        int b2 = find_bin(cnt, (unsigned)needed, wu, &s_bin, &s_above);
        thrkey = (unsigned)b2 << 19;
        if (t == 0) s_cnt = 0;
        __syncthreads();
        for (int ii = t; ii < V4; ii += NTHREADS) {
            float4 v = x4[ii];
            unsigned u;
            u = mono(v.x); if (u >= thrkey) { int p = atomicAdd(&s_cnt, 1); if (p < CAP) key[p] = ((unsigned long long)u << 32) | (unsigned)~(unsigned)(4 * ii + 0); }
            u = mono(v.y); if (u >= thrkey) { int p = atomicAdd(&s_cnt, 1); if (p < CAP) key[p] = ((unsigned long long)u << 32) | (unsigned)~(unsigned)(4 * ii + 1); }
            u = mono(v.z); if (u >= thrkey) { int p = atomicAdd(&s_cnt, 1); if (p < CAP) key[p] = ((unsigned long long)u << 32) | (unsigned)~(unsigned)(4 * ii + 2); }
            u = mono(v.w); if (u >= thrkey) { int p = atomicAdd(&s_cnt, 1); if (p < CAP) key[p] = ((unsigned long long)u << 32) | (unsigned)~(unsigned)(4 * ii + 3); }
        }
        for (int j = (V4 << 2) + t; j < V; j += NTHREADS) {
            unsigned u = mono(x[j]);
            if (u >= thrkey) { int p = atomicAdd(&s_cnt, 1); if (p < CAP) key[p] = ((unsigned long long)u << 32) | (unsigned)~(unsigned)j; }
        }
        __syncthreads();
    }
    const int n = min(s_cnt, CAP);
    const float lZ = s_lz;

    // ------------- counting sort: key[0..n) -> keyB[0..n) ascending -----------
    for (int z = t; z < NBINS; z += NTHREADS) cnt[z] = 0u;
    __syncthreads();
    const unsigned range = s_kmax - thrkey;
    const int nbits = 32 - __clz(range | 1u);
    const int shift = nbits > HBITS ? nbits - HBITS : 0;
    for (int z = t; z < n; z += NTHREADS) {
        unsigned u = (unsigned)(key[z] >> 32);
        atomicAdd(&cnt[(u - thrkey) >> shift], 1u);
    }
    __syncthreads();
    excl_scan(cnt, wu);                     // cnt = exclusive offsets (syncs inside)
    for (int z = t; z < n; z += NTHREADS) {
        unsigned long long k = key[z];
        unsigned u = (unsigned)(k >> 32);
        unsigned pos = atomicAdd(&cnt[(u - thrkey) >> shift], 1u);
        keyB[pos] = k;
    }
    __syncthreads();                        // cnt now = inclusive segment ends
#pragma unroll
    for (int j = 0; j < BPT; j++) {
        int bin = t * BPT + j;
        int st = bin ? (int)cnt[bin - 1] : 0;
        int en = (int)cnt[bin];
        for (int i2 = st + 1; i2 < en; i2++) {
            unsigned long long kv = keyB[i2];
            int j2 = i2 - 1;
            while (j2 >= st && keyB[j2] > kv) { keyB[j2 + 1] = keyB[j2]; j2--; }
            keyB[j2 + 1] = kv;
        }
    }
    __syncthreads();

#define DKEY(r) (keyB[n - 1 - (r)])
#define DVAL(r) inv_mono((unsigned)(DKEY(r) >> 32))
#define DIDX(r) ((int)(~(unsigned)DKEY(r)))

    // ---------------- per-row scalars (rmax = top candidate) ------------------
    const float rmax = DVAL(0);
    const float temp = temperature[row];
    const float mp   = min_p[row];
    const float tp   = top_p[row];
    const int kk_ = kclip;
    const float t_mp = rmax + temp * logf(mp);
    const int npad = ((n + NTHREADS - 1) / NTHREADS) * NTHREADS;

    for (int r = t; r < npad; r += NTHREADS) {
        bool pred = (r < n) && (DVAL(r) >= t_mp);
        unsigned bl = __ballot_sync(0xFFFFFFFFu, pred);
        if (lane == 0 && bl) atomicAdd(&s_m, __popc(bl));
    }
    __syncthreads();
    const int mcnt = s_m;

    if (mcnt >= kk_) {
        float kth = DVAL(kk_ - 1);
        for (int r = t; r < npad; r += NTHREADS) {
            bool pred = (r < n) && (DVAL(r) >= kth);
            unsigned bl = __ballot_sync(0xFFFFFFFFu, pred);
            if (lane == 0 && bl) atomicAdd(&s_S, __popc(bl));
        }
    }
    __syncthreads();
    const int S = (mcnt >= kk_) ? min(s_S, CAP) : mcnt;

    const bool greedy = (temp < SAMPLING_EPS);
    int sampled, rstar;

    if (!greedy) {
        const float lt0 = DVAL(0) / temp;
        for (int r = t; r < CAP; r += NTHREADS) {
            float ev = 0.f;
            if (r < S) ev = __expf(DVAL(r) / temp - lt0);
            e[r] = ev;                       // overlays cnt (sort done)
        }
        __syncthreads();

        float a0 = e[2 * t], a1 = e[2 * t + 1];
        float tsum = a0 + a1;
        float sv = tsum;
#pragma unroll
        for (int off = 1; off < 32; off <<= 1) {
            float nb = __shfl_up_sync(0xFFFFFFFFu, sv, off);
            if (lane >= off) sv += nb;
        }
        if (lane == 31) wf[warp] = sv;
        __syncthreads();
        if (warp == 0) {
            float wv = wf[lane];
#pragma unroll
            for (int off = 1; off < 32; off <<= 1) {
                float nb = __shfl_up_sync(0xFFFFFFFFu, wv, off);
                if (lane >= off) wv += nb;
            }
            wf[lane] = wv;
        }
        __syncthreads();
        float inclf = sv + (warp ? wf[warp - 1] : 0.f);
        const float Z = wf[NWARPS - 1];
        float excl = inclf - tsum;
        hd[2 * t]     = excl;
        hd[2 * t + 1] = excl + a0;
        __syncthreads();

        const float c1f = (1.f - tp) * Z;
        const float* __restrict__ qrow = q + (size_t)row * V;
        float best = -1.f;
        int bidx = 0x7FFFFFFF, brr = 0;
        for (int r = t; r < S; r += NTHREADS) {
            if (r == 0 || (Z - hd[r]) > c1f) {
                int id = DIDX(r);
                float qv = qrow[id];
                float ex = -logf(fmaxf(qv, 1e-10f));
                float sc = e[r] / ex;
                if (sc > best || (sc == best && id < bidx)) { best = sc; bidx = id; brr = r; }
            }
        }
#pragma unroll
        for (int off = 16; off; off >>= 1) {
            float ob = __shfl_down_sync(0xFFFFFFFFu, best, off);
            int   oi = __shfl_down_sync(0xFFFFFFFFu, bidx, off);
            int   orr = __shfl_down_sync(0xFFFFFFFFu, brr, off);
            if (ob > best || (ob == best && oi < bidx)) { best = ob; bidx = oi; brr = orr; }
        }
        if (lane == 0) { wf[warp] = best; wi[warp] = bidx; wr[warp] = brr; }
        __syncthreads();
        if (warp == 0) {
            best = wf[lane]; bidx = wi[lane]; brr = wr[lane];
#pragma unroll
            for (int off = 16; off; off >>= 1) {
                float ob = __shfl_down_sync(0xFFFFFFFFu, best, off);
                int   oi = __shfl_down_sync(0xFFFFFFFFu, bidx, off);
                int   orr = __shfl_down_sync(0xFFFFFFFFu, brr, off);
                if (ob > best || (ob == best && oi < bidx)) { best = ob; bidx = oi; brr = orr; }
            }
            if (lane == 0) { s_sampled = bidx; s_rstar = brr; }
        }
        __syncthreads();
        sampled = s_sampled;
        rstar = s_rstar;
    } else {
        sampled = DIDX(0);
        rstar = 0;
    }

    // rank: #values >= sampled value (lZ cancels)
    const float vstar = DVAL(rstar);
    for (int r = t; r < npad; r += NTHREADS) {
        bool pred = (r < n) && (DVAL(r) >= vstar);
        unsigned bl = __ballot_sync(0xFFFFFFFFu, pred);
        if (lane == 0 && bl) atomicAdd(&s_rank, __popc(bl));
    }
    __syncthreads();

    const float tlp = vstar - lZ;
    if (t == 0) {
        out[row] = (float)sampled;
        out[(size_t)B + (size_t)row * C] = (float)sampled;
        out[(size_t)B + (size_t)B * C + (size_t)row * C] = tlp;
        out[(size_t)B + 2 * (size_t)B * C + row] = (float)s_rank;
    }
    if (t >= 1 && t < C) {
        int r = t - 1;
        unsigned long long kv = DKEY(r);
        out[(size_t)B + (size_t)row * C + t] = (float)(~(unsigned)kv);
        out[(size_t)B + (size_t)B * C + (size_t)row * C + t] = inv_mono((unsigned)(kv >> 32)) - lZ;
    }
#undef DKEY
#undef DVAL
#undef DIDX
}

// ======================================================================
extern "C" void kernel_launch(void* const* d_in, const int* in_sizes, int n_in,
                              void* d_out, int out_size) {
    const float* logits      = (const float*)d_in[0];
    const float* temperature = (const float*)d_in[1];
    const float* min_p       = (const float*)d_in[2];
    const int*   top_k       = (const int*)d_in[3];
    const float* top_p       = (const float*)d_in[4];
    const float* q           = (const float*)d_in[5];

    int B = in_sizes[1];
    int V = in_sizes[0] / B;
    int C = (out_size / B - 2) / 2;   // num_logprobs + 1

    cudaFuncSetAttribute(sampler_fused,
                         cudaFuncAttributeMaxDynamicSharedMemorySize, SMEMSZ);
    sampler_fused<<<B, NTHREADS, SMEMSZ>>>(logits, temperature, min_p, top_k,
                                           top_p, q, (float*)d_out, B, V, C);
}